// round 17
// baseline (speedup 1.0000x reference)
#include <cuda_runtime.h>
#include <cuda_bf16.h>
#include <cuda_fp16.h>
#include <cstdint>

#define Bsz 1024
#define Nn  256
#define Dd  64
#define LAT 128
#define EC  32
#define NTHREADS 256

// Row strides (bytes): 64 bf16 + 16B pad = 144 (bank step 4/row -> CF ldmatrix);
// 32 bf16 + 16B pad = 80 (bank step 20/row -> CF).
#define SA 144
#define SE 80

// SMEM — weights + reduction only (A lives in registers): 38KB/CTA
#define OFF_WF   0u        // Wf [128][144] = 18432
#define OFF_WC   18432u    // Wc [32][144]  = 4608
#define OFF_WA   23040u    // Wa2[128][80]  = 10240 (pre-scaled by log2e)
#define OFF_BC   33280u    // 32 f32
#define OFF_BFB  33408u    // 128 f32
#define OFF_RED  33920u    // 8*132 u32 (packed {S:f16, W:f16}) = 4224
#define SMEM_TOTAL 38144u
// Overlays inside OFF_RED (col-owned, after combine): sAgg=row0, sP4=rows1-2

__device__ __forceinline__ uint32_t smem_u32(const void* p) {
    uint32_t a;
    asm("{ .reg .u64 t; cvta.to.shared.u64 t, %1; cvt.u32.u64 %0, t; }" : "=r"(a) : "l"(p));
    return a;
}
__device__ __forceinline__ void ldsm4(uint32_t& r0, uint32_t& r1, uint32_t& r2,
                                      uint32_t& r3, uint32_t addr) {
    asm volatile("ldmatrix.sync.aligned.m8n8.x4.shared.b16 {%0,%1,%2,%3}, [%4];"
                 : "=r"(r0), "=r"(r1), "=r"(r2), "=r"(r3) : "r"(addr));
}
__device__ __forceinline__ void mma_bf16(float d[4], uint32_t a0, uint32_t a1,
                                         uint32_t a2, uint32_t a3,
                                         uint32_t b0, uint32_t b1) {
    asm volatile(
        "mma.sync.aligned.m16n8k16.row.col.f32.bf16.bf16.f32 "
        "{%0,%1,%2,%3}, {%4,%5,%6,%7}, {%8,%9}, {%0,%1,%2,%3};"
        : "+f"(d[0]), "+f"(d[1]), "+f"(d[2]), "+f"(d[3])
        : "r"(a0), "r"(a1), "r"(a2), "r"(a3), "r"(b0), "r"(b1));
}
__device__ __forceinline__ uint32_t cvt2(float v0, float v1) {
    __nv_bfloat162 h2 = __float22bfloat162_rn(make_float2(v0, v1));
    return *reinterpret_cast<uint32_t*>(&h2);
}
__device__ __forceinline__ float ex2(float x) {
    float r;
    asm("ex2.approx.f32 %0, %1;" : "=f"(r) : "f"(x));
    return r;
}

extern __shared__ __align__(1024) char smem[];

__global__ void __launch_bounds__(NTHREADS, 2)
arm_mma16_kernel(const float* __restrict__ nb, const float* __restrict__ Wc,
                 const float* __restrict__ bc, const float* __restrict__ Wf,
                 const float* __restrict__ bf, const float* __restrict__ Wa,
                 const float* __restrict__ Wl, const float* __restrict__ bl,
                 float* __restrict__ out)
{
    const uint32_t sbase = smem_u32(smem);
    const int t = threadIdx.x;
    const int lane = t & 31, warp = t >> 5;   // 8 warps

    // ---------------- Stage bf16 weights ONCE per CTA ----------------
    {
        const float LOG2E = 1.4426950408889634f;
        #pragma unroll
        for (int it = 0; it < 16; ++it) {             // Wf^T: 128n x 32 d-pairs
            int idx = it * NTHREADS + t;
            int n = idx & 127, d0 = (idx >> 7) * 2;
            *(uint32_t*)(smem + OFF_WF + n * SA + d0 * 2) =
                cvt2(Wf[d0 * LAT + n], Wf[(d0 + 1) * LAT + n]);
        }
        #pragma unroll
        for (int it = 0; it < 4; ++it) {              // Wc^T: 32e x 32 d-pairs
            int idx = it * NTHREADS + t;
            int e = idx & 31, d0 = (idx >> 5) * 2;
            *(uint32_t*)(smem + OFF_WC + e * SA + d0 * 2) =
                cvt2(Wc[d0 * EC + e], Wc[(d0 + 1) * EC + e]);
        }
        #pragma unroll
        for (int it = 0; it < 8; ++it) {              // Wa2^T * log2e: 128n x 16 e-pairs
            int idx = it * NTHREADS + t;
            int n = idx & 127, e0 = (idx >> 7) * 2;
            *(uint32_t*)(smem + OFF_WA + n * SE + e0 * 2) =
                cvt2(LOG2E * Wa[(EC + e0) * LAT + n],
                     LOG2E * Wa[(EC + e0 + 1) * LAT + n]);
        }
        if (t < EC)  ((float*)(smem + OFF_BC))[t]  = bc[t];
        if (t < LAT) ((float*)(smem + OFF_BFB))[t] = bf[t];
    }
    __syncthreads();

    // ---------------- Fragment lane constants ----------------
    const int brow = ((lane >> 4) << 3) + (lane & 7);
    const int bcolB = (((lane >> 3) & 1) << 3) * 2;
    const int cpair = (lane & 3) * 2;
    const int rquad = lane >> 2;
    const int R0 = warp * 32;                          // warp owns rows R0..R0+31

    float* sbc  = (float*)(smem + OFF_BC);
    float* sbfb = (float*)(smem + OFF_BFB);
    uint32_t* sRed = (uint32_t*)(smem + OFF_RED);      // [8][132] packed {S,W} f16
    float* sAgg = (float*)(smem + OFF_RED);            // overlay row 0
    float* sP4  = (float*)(smem + OFF_RED + 528u);     // overlay rows 1-2

    // ---------------- Batch loop (persistent, 2 CTAs/SM) ----------------
    for (int bb = blockIdx.x; bb < Bsz; bb += gridDim.x) {

        // ---- Load A fragments DIRECTLY from gmem into registers.
        //      m16k16 A layout: a0=(r,c0..1) a1=(r+8,c0..1) a2=(r,c0+8..9)
        //      a3=(r+8,c0+8..9), r = R0+16mt+rquad, c0 = cpair+16ks. ----
        uint32_t aF[2][4][4];
        {
            const float* Ab = nb + (size_t)bb * Nn * Dd;
            #pragma unroll
            for (int mt = 0; mt < 2; ++mt)
                #pragma unroll
                for (int ks = 0; ks < 4; ++ks) {
                    const float* pa = Ab + (size_t)(R0 + mt * 16 + rquad) * Dd
                                       + ks * 16 + cpair;
                    float2 v0 = *(const float2*)(pa);
                    float2 v1 = *(const float2*)(pa + 8 * Dd);
                    float2 v2 = *(const float2*)(pa + 8);
                    float2 v3 = *(const float2*)(pa + 8 * Dd + 8);
                    aF[mt][ks][0] = cvt2(v0.x, v0.y);
                    aF[mt][ks][1] = cvt2(v1.x, v1.y);
                    aF[mt][ks][2] = cvt2(v2.x, v2.y);
                    aF[mt][ks][3] = cvt2(v3.x, v3.y);
                }
            int bnext = bb + gridDim.x;
            if (bnext < Bsz) {
                const char* pn = (const char*)(nb + (size_t)bnext * Nn * Dd);
                #pragma unroll
                for (int it = 0; it < 16; ++it)
                    asm volatile("prefetch.global.L2 [%0];"
                                 :: "l"(pn + (size_t)(it * NTHREADS + t) * 16));
            }
        }

        // ---- E = A @ Wc + bc (rows R0..R0+31, all 32 e-cols, K=64) ----
        float eacc[2][4][4];
        #pragma unroll
        for (int mt = 0; mt < 2; ++mt)
            #pragma unroll
            for (int nt = 0; nt < 4; ++nt) {
                float b0 = sbc[nt * 8 + cpair], b1 = sbc[nt * 8 + cpair + 1];
                eacc[mt][nt][0] = b0; eacc[mt][nt][1] = b1;
                eacc[mt][nt][2] = b0; eacc[mt][nt][3] = b1;
            }
        {
            uint32_t bOff = sbase + OFF_WC + (uint32_t)(brow * SA) + bcolB;
            #pragma unroll
            for (int ks = 0; ks < 4; ++ks) {
                uint32_t p0, p1, p2, p3, q0, q1, q2, q3;
                ldsm4(p0, p1, p2, p3, bOff + ks * 32);
                ldsm4(q0, q1, q2, q3, bOff + 16 * SA + ks * 32);
                #pragma unroll
                for (int mt = 0; mt < 2; ++mt) {
                    mma_bf16(eacc[mt][0], aF[mt][ks][0], aF[mt][ks][1],
                             aF[mt][ks][2], aF[mt][ks][3], p0, p1);
                    mma_bf16(eacc[mt][1], aF[mt][ks][0], aF[mt][ks][1],
                             aF[mt][ks][2], aF[mt][ks][3], p2, p3);
                    mma_bf16(eacc[mt][2], aF[mt][ks][0], aF[mt][ks][1],
                             aF[mt][ks][2], aF[mt][ks][3], q0, q1);
                    mma_bf16(eacc[mt][3], aF[mt][ks][0], aF[mt][ks][1],
                             aF[mt][ks][2], aF[mt][ks][3], q2, q3);
                }
            }
        }
        // ---- Pack relu(E) accumulators DIRECTLY into L's A-fragments
        //      (acc layout == A-fragment layout; no smem round trip). ----
        uint32_t eaF[2][2][4];
        #pragma unroll
        for (int mt = 0; mt < 2; ++mt)
            #pragma unroll
            for (int kc = 0; kc < 2; ++kc) {
                int nA = kc * 2, nB = kc * 2 + 1;
                eaF[mt][kc][0] = cvt2(fmaxf(eacc[mt][nA][0], 0.f), fmaxf(eacc[mt][nA][1], 0.f));
                eaF[mt][kc][1] = cvt2(fmaxf(eacc[mt][nA][2], 0.f), fmaxf(eacc[mt][nA][3], 0.f));
                eaF[mt][kc][2] = cvt2(fmaxf(eacc[mt][nB][0], 0.f), fmaxf(eacc[mt][nB][1], 0.f));
                eaF[mt][kc][3] = cvt2(fmaxf(eacc[mt][nB][2], 0.f), fmaxf(eacc[mt][nB][3], 0.f));
            }

        // ---- 8 col-chunks of 16: L (A regs) -> ex2 -> F (A regs) -> reduce ----
        #pragma unroll 1
        for (int nc = 0; nc < 8; ++nc) {
            const int C = nc * 16;
            // L' = E' @ (Wa2*log2e)
            float lacc[2][2][4];
            #pragma unroll
            for (int mt = 0; mt < 2; ++mt)
                #pragma unroll
                for (int nt = 0; nt < 2; ++nt)
                    #pragma unroll
                    for (int i = 0; i < 4; ++i) lacc[mt][nt][i] = 0.f;
            {
                uint32_t bOff = sbase + OFF_WA + (uint32_t)((C + brow) * SE) + bcolB;
                #pragma unroll
                for (int kc = 0; kc < 2; ++kc) {
                    uint32_t p0, p1, p2, p3;
                    ldsm4(p0, p1, p2, p3, bOff + kc * 32);
                    #pragma unroll
                    for (int mt = 0; mt < 2; ++mt) {
                        mma_bf16(lacc[mt][0], eaF[mt][kc][0], eaF[mt][kc][1],
                                 eaF[mt][kc][2], eaF[mt][kc][3], p0, p1);
                        mma_bf16(lacc[mt][1], eaF[mt][kc][0], eaF[mt][kc][1],
                                 eaF[mt][kc][2], eaF[mt][kc][3], p2, p3);
                    }
                }
            }
            // u = 2^(L') (|logit| < ~3.5: max-subtraction provably unneeded)
            #pragma unroll
            for (int mt = 0; mt < 2; ++mt)
                #pragma unroll
                for (int nt = 0; nt < 2; ++nt)
                    #pragma unroll
                    for (int i = 0; i < 4; ++i) lacc[mt][nt][i] = ex2(lacc[mt][nt][i]);

            // F = A @ Wf + bf (A fragments already in registers)
            float facc[2][2][4];
            #pragma unroll
            for (int mt = 0; mt < 2; ++mt)
                #pragma unroll
                for (int nt = 0; nt < 2; ++nt) {
                    float b0 = sbfb[C + nt * 8 + cpair], b1 = sbfb[C + nt * 8 + cpair + 1];
                    facc[mt][nt][0] = b0; facc[mt][nt][1] = b1;
                    facc[mt][nt][2] = b0; facc[mt][nt][3] = b1;
                }
            {
                uint32_t bOff = sbase + OFF_WF + (uint32_t)((C + brow) * SA) + bcolB;
                #pragma unroll
                for (int ks = 0; ks < 4; ++ks) {
                    uint32_t p0, p1, p2, p3;
                    ldsm4(p0, p1, p2, p3, bOff + ks * 32);
                    #pragma unroll
                    for (int mt = 0; mt < 2; ++mt) {
                        mma_bf16(facc[mt][0], aF[mt][ks][0], aF[mt][ks][1],
                                 aF[mt][ks][2], aF[mt][ks][3], p0, p1);
                        mma_bf16(facc[mt][1], aF[mt][ks][0], aF[mt][ks][1],
                                 aF[mt][ks][2], aF[mt][ks][3], p2, p3);
                    }
                }
            }

            // Row sums over this warp's 32 rows (u, u*relu(F))
            float sp[2][2], wp[2][2];
            #pragma unroll
            for (int nt = 0; nt < 2; ++nt) { sp[nt][0] = sp[nt][1] = wp[nt][0] = wp[nt][1] = 0.f; }
            #pragma unroll
            for (int nt = 0; nt < 2; ++nt)
                #pragma unroll
                for (int mt = 0; mt < 2; ++mt) {
                    float u0 = lacc[mt][nt][0], u1 = lacc[mt][nt][1];
                    float u2 = lacc[mt][nt][2], u3 = lacc[mt][nt][3];
                    sp[nt][0] += u0 + u2;
                    sp[nt][1] += u1 + u3;
                    wp[nt][0] += u0 * fmaxf(facc[mt][nt][0], 0.f)
                               + u2 * fmaxf(facc[mt][nt][2], 0.f);
                    wp[nt][1] += u1 * fmaxf(facc[mt][nt][1], 0.f)
                               + u3 * fmaxf(facc[mt][nt][3], 0.f);
                }
            #pragma unroll
            for (int s = 4; s < 32; s <<= 1) {
                #pragma unroll
                for (int nt = 0; nt < 2; ++nt) {
                    sp[nt][0] += __shfl_xor_sync(0xFFFFFFFFu, sp[nt][0], s);
                    sp[nt][1] += __shfl_xor_sync(0xFFFFFFFFu, sp[nt][1], s);
                    wp[nt][0] += __shfl_xor_sync(0xFFFFFFFFu, wp[nt][0], s);
                    wp[nt][1] += __shfl_xor_sync(0xFFFFFFFFu, wp[nt][1], s);
                }
            }
            if (rquad == 0) {
                #pragma unroll
                for (int nt = 0; nt < 2; ++nt) {
                    int c = C + nt * 8 + cpair;
                    __half2 v0 = __floats2half2_rn(sp[nt][0], wp[nt][0]);
                    __half2 v1 = __floats2half2_rn(sp[nt][1], wp[nt][1]);
                    sRed[warp * 132 + c]     = *reinterpret_cast<uint32_t*>(&v0);
                    sRed[warp * 132 + c + 1] = *reinterpret_cast<uint32_t*>(&v1);
                }
            }
        }
        __syncthreads();

        // ---- Combine 8 warp partials; agg = W/S (overlay, col-owned) ----
        if (t < LAT) {
            float S = 0.f, W = 0.f;
            #pragma unroll
            for (int w = 0; w < 8; ++w) {
                uint32_t v = sRed[w * 132 + t];
                __half2 h = *reinterpret_cast<__half2*>(&v);
                S += __low2float(h);
                W += __high2float(h);
            }
            sAgg[t] = W / S;
        }
        __syncthreads();

        // ---- out[bb] = relu(agg @ Wl + bl) ----
        {
            const int q = t >> 7, k = t & 127;     // q in {0,1}: 64 j each
            float p4 = 0.f;
            #pragma unroll 8
            for (int j = 0; j < 64; ++j) {
                int jj = q * 64 + j;
                p4 = fmaf(sAgg[jj], __ldg(&Wl[jj * LAT + k]), p4);
            }
            sP4[q * 132 + k] = p4;
        }
        __syncthreads();
        if (t < LAT)
            out[(size_t)bb * LAT + t] =
                fmaxf(__ldg(&bl[t]) + sP4[t] + sP4[132 + t], 0.f);
        __syncthreads();   // protect sRed overlays before next batch
    }
}

extern "C" void kernel_launch(void* const* d_in, const int* in_sizes, int n_in,
                              void* d_out, int out_size) {
    // metadata order: local_data, neighbor_data, Wc, bc, Wf, bf, Wa, ba, Wl, bl
    // local_data and ba provably unused (softmax shift-invariance over n).
    const float* nb = (const float*)d_in[1];
    const float* Wc = (const float*)d_in[2];
    const float* bc = (const float*)d_in[3];
    const float* Wf = (const float*)d_in[4];
    const float* bf = (const float*)d_in[5];
    const float* Wa = (const float*)d_in[6];
    const float* Wl = (const float*)d_in[8];
    const float* bl = (const float*)d_in[9];
    float* out = (float*)d_out;

    int sms = 152;
    cudaDeviceGetAttribute(&sms, cudaDevAttrMultiProcessorCount, 0);
    if (sms < 1) sms = 152;
    int grid = 2 * sms;
    if (grid > Bsz) grid = Bsz;

    cudaFuncSetAttribute(arm_mma16_kernel,
                         cudaFuncAttributeMaxDynamicSharedMemorySize, (int)SMEM_TOTAL);
    arm_mma16_kernel<<<grid, NTHREADS, SMEM_TOTAL>>>(nb, Wc, bc, Wf, bf, Wa, Wl, bl, out);
}